// round 7
// baseline (speedup 1.0000x reference)
#include <cuda_runtime.h>

#define HEADS   8
#define NTOK    4096
#define RANK    820        /* # elements strictly below threshold */
#define ROWS    4
#define THREADS 256
#define TPT     16         /* tokens per thread */
#define CAPR    384        /* candidate buffer per row */
#define NREG    12         /* CAPR/32 */

// ---------------- device scratch ----------------
__device__ float  g_qraw[32 * NTOK];      // [head*4+c][n]
__device__ float4 g_kT  [HEADS * NTOK];   // [head][n] -> (c0,c1,c2,c3)
__device__ float4 g_vT  [HEADS * NTOK];
__device__ float  g_qs[32];
__device__ float  g_ks[32];
__device__ float  g_pre[128 * 1024];      // attention output in proj layout [ch][pixel]

// ---------------- kernel 1: qkv = 1x1x1 group conv + depthwise 3x3 ----------------
__global__ void prep_kernel(const float* __restrict__ x,
                            const float* __restrict__ wqkv,
                            const float* __restrict__ wdw) {
    __shared__ float sh[34][34];
    int o  = blockIdx.x;
    int cd = blockIdx.y;
    int tid = threadIdx.x;
    for (int i = tid; i < 34 * 34; i += THREADS) ((float*)sh)[i] = 0.f;
    __syncthreads();
    float w0 = wqkv[o * 4 + 0], w1 = wqkv[o * 4 + 1];
    float w2 = wqkv[o * 4 + 2], w3 = wqkv[o * 4 + 3];
    for (int p = tid; p < 1024; p += THREADS) {
        int y = p >> 5, xx = p & 31;
        float v = w0 * x[(0 * 32 + cd) * 1024 + p]
                + w1 * x[(1 * 32 + cd) * 1024 + p]
                + w2 * x[(2 * 32 + cd) * 1024 + p]
                + w3 * x[(3 * 32 + cd) * 1024 + p];
        sh[y + 1][xx + 1] = v;
    }
    __syncthreads();
    float k00 = wdw[o*9+0], k01 = wdw[o*9+1], k02 = wdw[o*9+2];
    float k10 = wdw[o*9+3], k11 = wdw[o*9+4], k12 = wdw[o*9+5];
    float k20 = wdw[o*9+6], k21 = wdw[o*9+7], k22 = wdw[o*9+8];
    int g = o >> 2, tt = o & 3;
    int head = cd >> 2, c = cd & 3;
    for (int p = tid; p < 1024; p += THREADS) {
        int y = p >> 5, xx = p & 31;
        float s = k00*sh[y  ][xx] + k01*sh[y  ][xx+1] + k02*sh[y  ][xx+2]
                + k10*sh[y+1][xx] + k11*sh[y+1][xx+1] + k12*sh[y+1][xx+2]
                + k20*sh[y+2][xx] + k21*sh[y+2][xx+1] + k22*sh[y+2][xx+2];
        int n = (p << 2) + tt;
        if (g == 0)      g_qraw[cd * NTOK + n] = s;
        else if (g == 1) ((float*)g_kT)[(head * NTOK + n) * 4 + c] = s;
        else             ((float*)g_vT)[(head * NTOK + n) * 4 + c] = s;
    }
}

// ---------------- kernel 2: per-(head,c) L2 norms of q and k ----------------
__global__ void norm_kernel() {
    int i = blockIdx.x;
    int tid = threadIdx.x;
    float s = 0.f;
    if (i < 32) {
        const float* q = g_qraw + i * NTOK;
        for (int n = tid; n < NTOK; n += THREADS) { float v = q[n]; s += v * v; }
    } else {
        int j = i - 32; int head = j >> 2, c = j & 3;
        const float* k = ((const float*)g_kT) + head * NTOK * 4 + c;
        for (int n = tid; n < NTOK; n += THREADS) { float v = k[n * 4]; s += v * v; }
    }
    __shared__ float red[8];
    for (int off = 16; off; off >>= 1) s += __shfl_down_sync(0xffffffffu, s, off);
    if ((tid & 31) == 0) red[tid >> 5] = s;
    __syncthreads();
    if (tid == 0) {
        float t = 0.f;
        for (int w = 0; w < 8; w++) t += red[w];
        float scale = 1.f / fmaxf(sqrtf(t), 1e-12f);
        if (i < 32) g_qs[i] = scale; else g_ks[i - 32] = scale;
    }
}

// ---------------- kernel 3: scores in REGISTERS, no score smem ----------------
__device__ __forceinline__ unsigned ordkey(float f) {
    unsigned u = __float_as_uint(f);
    return u ^ (0x80000000u | (unsigned)((int)u >> 31));
}
__device__ __forceinline__ float inv_ordkey(unsigned u) {
    return __uint_as_float(u ^ (0x80000000u | ~(unsigned)((int)u >> 31)));
}
__device__ __forceinline__ unsigned next_pivot(unsigned lo, unsigned hi, int clo, int chi, int useInterp) {
    unsigned span = hi - lo;
    unsigned step;
    if (!useInterp) step = span >> 1;
    else {
        float fr = (float)(RANK + 1 - clo) / (float)(chi - clo);
        step = (unsigned)(fr * (float)span);
        unsigned mn = span >> 4; if (!mn) mn = 1;
        if (step < mn) step = mn;
        if (step > span - mn) step = span - mn;
    }
    if (!step) step = 1;
    return lo + step;
}

__global__ void __launch_bounds__(THREADS, 2) attn_kernel(const float* __restrict__ temperature) {
    __shared__ unsigned buf[ROWS * CAPR];
    __shared__ unsigned cnt[4];
    __shared__ unsigned state[4];        // 0=bisect 1=buffer-search 2=done 3=compact-pending
    __shared__ unsigned slo[4], shi[4];
    __shared__ int      sclo[4], schi[4];
    __shared__ unsigned spiv[4], stkey[4], stgt[4], sukey[4];
    __shared__ float    smaxf[4];
    __shared__ float    spvf[8];         // two float pivots per row
    __shared__ int      sany[1];
    __shared__ unsigned gcnt[8];
    __shared__ unsigned wred[96];
    __shared__ float    sred[160];
    __shared__ float    sfin[20];

    int bx   = blockIdx.x;
    int head = bx >> 10;
    int n0   = (bx & 1023) << 2;
    int tid  = threadIdx.x;
    int lane = tid & 31, wid = tid >> 5;

    float temp = temperature[head];
    float4 cf[ROWS];
    #pragma unroll
    for (int r = 0; r < ROWS; r++) {
        int n = n0 + r;
        float a0 = g_qraw[(head*4+0)*NTOK + n] * g_qs[head*4+0] * g_ks[head*4+0] * temp;
        float a1 = g_qraw[(head*4+1)*NTOK + n] * g_qs[head*4+1] * g_ks[head*4+1] * temp;
        float a2 = g_qraw[(head*4+2)*NTOK + n] * g_qs[head*4+2] * g_ks[head*4+2] * temp;
        float a3 = g_qraw[(head*4+3)*NTOK + n] * g_qs[head*4+3] * g_ks[head*4+3] * temp;
        cf[r] = make_float4(a0, a1, a2, a3);
    }

    // ---- pass 1: scores into registers, moments + max ----
    float sreg[ROWS][TPT];
    float fsum[ROWS] = {0,0,0,0}, fsq[ROWS] = {0,0,0,0};
    float fmax_[ROWS] = {-3.4e38f, -3.4e38f, -3.4e38f, -3.4e38f};
    const float4* kt = g_kT + head * NTOK;
    #pragma unroll
    for (int jo = 0; jo < 4; jo++) {
        int mb = (jo << 10) + (tid << 2);
        float4 k0 = __ldg(&kt[mb+0]);
        float4 k1 = __ldg(&kt[mb+1]);
        float4 k2 = __ldg(&kt[mb+2]);
        float4 k3 = __ldg(&kt[mb+3]);
        #pragma unroll
        for (int r = 0; r < ROWS; r++) {
            float s0 = fmaf(cf[r].x,k0.x, fmaf(cf[r].y,k0.y, fmaf(cf[r].z,k0.z, cf[r].w*k0.w)));
            float s1 = fmaf(cf[r].x,k1.x, fmaf(cf[r].y,k1.y, fmaf(cf[r].z,k1.z, cf[r].w*k1.w)));
            float s2 = fmaf(cf[r].x,k2.x, fmaf(cf[r].y,k2.y, fmaf(cf[r].z,k2.z, cf[r].w*k2.w)));
            float s3 = fmaf(cf[r].x,k3.x, fmaf(cf[r].y,k3.y, fmaf(cf[r].z,k3.z, cf[r].w*k3.w)));
            sreg[r][jo*4+0] = s0; sreg[r][jo*4+1] = s1;
            sreg[r][jo*4+2] = s2; sreg[r][jo*4+3] = s3;
            fsum[r] += (s0 + s1) + (s2 + s3);
            fsq[r]  += fmaf(s0,s0, fmaf(s1,s1, fmaf(s2,s2, s3*s3)));
            fmax_[r] = fmaxf(fmax_[r], fmaxf(fmaxf(s0,s1), fmaxf(s2,s3)));
        }
    }
    #pragma unroll
    for (int r = 0; r < ROWS; r++) {
        for (int off = 16; off; off >>= 1) {
            fmax_[r] = fmaxf(fmax_[r], __shfl_xor_sync(0xffffffffu, fmax_[r], off));
            fsum[r] += __shfl_xor_sync(0xffffffffu, fsum[r], off);
            fsq[r]  += __shfl_xor_sync(0xffffffffu, fsq[r],  off);
        }
    }
    if (lane == 0) {
        #pragma unroll
        for (int r = 0; r < ROWS; r++) {
            wred[wid*12 + r]     = __float_as_uint(fmax_[r]);
            wred[wid*12 + 4 + r] = __float_as_uint(fsum[r]);
            wred[wid*12 + 8 + r] = __float_as_uint(fsq[r]);
        }
    }
    __syncthreads();
    if (tid < 12) {
        int r = tid & 3, kind = tid >> 2;
        if (kind == 0) {
            float v = -3.4e38f;
            for (int w = 0; w < 8; w++) v = fmaxf(v, __uint_as_float(wred[w*12 + r]));
            sukey[r] = ordkey(v); smaxf[r] = v;
        } else {
            float s = 0.f;
            for (int w = 0; w < 8; w++) s += __uint_as_float(wred[w*12 + kind*4 + r]);
            sfin[tid] = s;
        }
    }
    __syncthreads();
    if (tid < 4) {
        float mean = sfin[4 + tid] * (1.f / 4096.f);
        float var  = sfin[8 + tid] * (1.f / 4096.f) - mean * mean;
        float sig  = sqrtf(fmaxf(var, 0.f));
        spvf[tid*2 + 0] = fmaf(-0.9741f, sig, mean);   // quantile 0.165
        spvf[tid*2 + 1] = fmaf(-0.7225f, sig, mean);   // quantile 0.235
        cnt[tid] = 0;
    }
    __syncthreads();

    // ---- scan (registers): counts below both pivots + window compaction ----
    {
        float p1f[ROWS], p5f[ROWS];
        #pragma unroll
        for (int r = 0; r < ROWS; r++) { p1f[r] = spvf[r*2]; p5f[r] = spvf[r*2+1]; }
        int c1t[ROWS] = {0,0,0,0}, cwt[ROWS] = {0,0,0,0};
        #pragma unroll
        for (int r = 0; r < ROWS; r++) {
            #pragma unroll
            for (int i = 0; i < TPT; i++) {
                float s = sreg[r][i];
                c1t[r] += (s < p1f[r]);
                cwt[r] += (s >= p1f[r]) & (s < p5f[r]);
            }
        }
        // compaction: per-thread atomic base, serial writes
        #pragma unroll
        for (int r = 0; r < ROWS; r++) {
            if (cwt[r]) {
                unsigned bs = atomicAdd(&cnt[r], (unsigned)cwt[r]);
                if (bs + (unsigned)cwt[r] <= CAPR) {
                    unsigned p = bs;
                    #pragma unroll
                    for (int i = 0; i < TPT; i++) {
                        float s = sreg[r][i];
                        if ((s >= p1f[r]) & (s < p5f[r])) buf[r * CAPR + p++] = ordkey(s);
                    }
                }
            }
        }
        // block-reduce counts
        int c1[ROWS], c5[ROWS];
        #pragma unroll
        for (int r = 0; r < ROWS; r++) {
            c1[r] = __reduce_add_sync(0xffffffffu, c1t[r]);
            c5[r] = __reduce_add_sync(0xffffffffu, c1t[r] + cwt[r]);
        }
        if (lane == 0) {
            #pragma unroll
            for (int r = 0; r < ROWS; r++) { wred[wid*8 + r] = (unsigned)c1[r]; wred[wid*8 + 4 + r] = (unsigned)c5[r]; }
        }
    }
    __syncthreads();
    if (tid < 8) {
        unsigned s = 0;
        for (int w = 0; w < 8; w++) s += wred[w*8 + tid];
        gcnt[tid] = s;
    }
    __syncthreads();

    // ---- classify rows ----
    if (tid < 4) {
        int c1v = (int)gcnt[tid], c5v = (int)gcnt[4 + tid];
        unsigned p1 = ordkey(spvf[tid*2]), p5 = ordkey(spvf[tid*2 + 1]);
        if (c1v <= RANK && RANK < c5v && (c5v - c1v) <= CAPR) {
            state[tid] = 1; slo[tid] = p1; shi[tid] = p5; stgt[tid] = (unsigned)(RANK - c1v);
        } else {
            unsigned lo, hi; int clo, chi;
            if (RANK < c1v)      { lo = 0u; hi = p1; clo = 0;   chi = c1v; }
            else if (RANK < c5v) { lo = p1; hi = p5; clo = c1v; chi = c5v; }
            else                 { lo = p5; hi = sukey[tid] + 1u; clo = c5v; chi = NTOK; }
            slo[tid] = lo; shi[tid] = hi; sclo[tid] = clo; schi[tid] = chi;
            if (hi - lo <= 1u)            { stkey[tid] = lo; state[tid] = 2; }
            else if (chi - clo <= CAPR)   { state[tid] = 3; }
            else { state[tid] = 0; spiv[tid] = next_pivot(lo, hi, clo, chi, 1); }
        }
    }

    // ---- fallback bisect loop (rare) ----
    for (int iter = 0; iter < 72; iter++) {
        __syncthreads();
        if (tid == 0)
            sany[0] = (state[0]==0) | (state[1]==0) | (state[2]==0) | (state[3]==0);
        __syncthreads();
        if (!sany[0]) break;
        float pvf[ROWS]; int act[ROWS];
        #pragma unroll
        for (int r = 0; r < ROWS; r++) { act[r] = (state[r] == 0); pvf[r] = inv_ordkey(spiv[r]); }
        int cr[ROWS] = {0,0,0,0};
        #pragma unroll
        for (int r = 0; r < ROWS; r++) {
            if (act[r]) {
                #pragma unroll
                for (int i = 0; i < TPT; i++) cr[r] += (sreg[r][i] < pvf[r]);
            }
        }
        #pragma unroll
        for (int r = 0; r < ROWS; r++) cr[r] = __reduce_add_sync(0xffffffffu, cr[r]);
        if (lane == 0) {
            #pragma unroll
            for (int r = 0; r < ROWS; r++) wred[wid*4 + r] = (unsigned)cr[r];
        }
        __syncthreads();
        if (tid < 4 && state[tid] == 0) {
            int tot = 0;
            for (int w = 0; w < 8; w++) tot += (int)wred[w*4 + tid];
            if (tot <= RANK) { slo[tid] = spiv[tid]; sclo[tid] = tot; }
            else             { shi[tid] = spiv[tid]; schi[tid] = tot; }
            unsigned lo = slo[tid], hi = shi[tid];
            int cc = schi[tid] - sclo[tid];
            if (hi - lo <= 1u)      { stkey[tid] = lo; state[tid] = 2; }
            else if (cc <= CAPR)    { state[tid] = 3; }
            else spiv[tid] = next_pivot(lo, hi, sclo[tid], schi[tid], !(iter & 1));
        }
    }
    __syncthreads();
    if (tid < 4) {
        if (state[tid] == 0) { stkey[tid] = slo[tid]; state[tid] = 2; } // safety
        if (state[tid] == 3) cnt[tid] = 0;
    }
    __syncthreads();

    // ---- fallback compaction (rows in state 3) ----
    {
        bool anyc = (state[0]==3) | (state[1]==3) | (state[2]==3) | (state[3]==3);
        if (anyc) {
            #pragma unroll
            for (int r = 0; r < ROWS; r++) {
                if (state[r] == 3) {
                    float lof = inv_ordkey(slo[r]);
                    float hif = inv_ordkey(shi[r]);
                    int nc = 0;
                    #pragma unroll
                    for (int i = 0; i < TPT; i++) {
                        float s = sreg[r][i];
                        nc += (s >= lof) & (s < hif);
                    }
                    if (nc) {
                        unsigned bs = atomicAdd(&cnt[r], (unsigned)nc);
                        if (bs + (unsigned)nc <= CAPR) {
                            unsigned p = bs;
                            #pragma unroll
                            for (int i = 0; i < TPT; i++) {
                                float s = sreg[r][i];
                                if ((s >= lof) & (s < hif)) buf[r * CAPR + p++] = ordkey(s);
                            }
                        }
                    }
                }
            }
            __syncthreads();
            if (tid < 4 && state[tid] == 3) {
                stgt[tid] = (unsigned)(RANK - sclo[tid]);
                state[tid] = 1;
            }
            __syncthreads();
        }
    }

    // ---- warp-register bisect over candidate buffer (1 warp / row) ----
    if (wid < 4 && state[wid] == 1) {
        int c = (int)cnt[wid]; if (c > CAPR) c = CAPR;
        unsigned cand[NREG];
        #pragma unroll
        for (int i = 0; i < NREG; i++) {
            int idx = i * 32 + lane;
            cand[i] = (idx < c) ? buf[wid * CAPR + idx] : 0xFFFFFFFFu;
        }
        unsigned lo = slo[wid], hi = shi[wid], tgt = stgt[wid];
        while (hi - lo > 1u) {
            unsigned mid = lo + ((hi - lo) >> 1);
            unsigned cb = 0;
            #pragma unroll
            for (int i = 0; i < NREG; i++) cb += (cand[i] < mid);
            cb = __reduce_add_sync(0xffffffffu, cb);
            if (cb <= tgt) lo = mid; else hi = mid;
        }
        if (lane == 0) stkey[wid] = lo;
    }
    __syncthreads();

    // ---- pass 3: masked softmax + p@v from registers ----
    float thrf[ROWS], mrow[ROWS];
    #pragma unroll
    for (int r = 0; r < ROWS; r++) { thrf[r] = inv_ordkey(stkey[r]); mrow[r] = smaxf[r]; }
    float zz[ROWS] = {0.f, 0.f, 0.f, 0.f};
    float4 acc[ROWS];
    #pragma unroll
    for (int r = 0; r < ROWS; r++) acc[r] = make_float4(0.f, 0.f, 0.f, 0.f);
    const float4* vt = g_vT + head * NTOK;
    #pragma unroll
    for (int jo = 0; jo < 4; jo++) {
        int mb = (jo << 10) + (tid << 2);
        float4 v0 = __ldg(&vt[mb+0]);
        float4 v1 = __ldg(&vt[mb+1]);
        float4 v2 = __ldg(&vt[mb+2]);
        float4 v3 = __ldg(&vt[mb+3]);
        #pragma unroll
        for (int r = 0; r < ROWS; r++) {
            float s0 = sreg[r][jo*4+0], s1 = sreg[r][jo*4+1];
            float s2 = sreg[r][jo*4+2], s3 = sreg[r][jo*4+3];
            float w0 = (s0 >= thrf[r]) ? __expf(s0 - mrow[r]) : 0.f;
            float w1 = (s1 >= thrf[r]) ? __expf(s1 - mrow[r]) : 0.f;
            float w2 = (s2 >= thrf[r]) ? __expf(s2 - mrow[r]) : 0.f;
            float w3 = (s3 >= thrf[r]) ? __expf(s3 - mrow[r]) : 0.f;
            zz[r] += ((w0 + w1) + (w2 + w3));
            acc[r].x += w0*v0.x + w1*v1.x + w2*v2.x + w3*v3.x;
            acc[r].y += w0*v0.y + w1*v1.y + w2*v2.y + w3*v3.y;
            acc[r].z += w0*v0.z + w1*v1.z + w2*v2.z + w3*v3.z;
            acc[r].w += w0*v0.w + w1*v1.w + w2*v2.w + w3*v3.w;
        }
    }

    // block-reduce 20 accumulators
    float vals[20];
    #pragma unroll
    for (int r = 0; r < ROWS; r++) {
        vals[r*5 + 0] = zz[r];
        vals[r*5 + 1] = acc[r].x; vals[r*5 + 2] = acc[r].y;
        vals[r*5 + 3] = acc[r].z; vals[r*5 + 4] = acc[r].w;
    }
    #pragma unroll
    for (int q = 0; q < 20; q++)
        for (int off = 16; off; off >>= 1)
            vals[q] += __shfl_down_sync(0xffffffffu, vals[q], off);
    if (lane == 0) {
        #pragma unroll
        for (int q = 0; q < 20; q++) sred[q*8 + wid] = vals[q];
    }
    __syncthreads();
    if (tid < 20) {
        float s = 0.f;
        for (int w = 0; w < 8; w++) s += sred[tid*8 + w];
        sfin[tid] = s;
    }
    __syncthreads();
    if (tid < 16) {
        int r = tid >> 2, c = tid & 3;
        float val = sfin[r*5 + 1 + c] / sfin[r*5 + 0];
        int n = n0 + r;
        int tt = n & 3, pixel = n >> 2;
        int ch = tt * 32 + head * 4 + c;
        g_pre[ch * 1024 + pixel] = val;
    }
}

// ---------------- kernel 4: final 1x1 projection ----------------
__global__ void proj_kernel(const float* __restrict__ wproj, float* __restrict__ out) {
    int idx = blockIdx.x * THREADS + threadIdx.x;
    int o = idx >> 10, p = idx & 1023;
    const float* w = wproj + o * 128;
    float s = 0.f;
    #pragma unroll 8
    for (int ch = 0; ch < 128; ch++) s += w[ch] * g_pre[ch * 1024 + p];
    out[idx] = s;
}

// ---------------- launch ----------------
extern "C" void kernel_launch(void* const* d_in, const int* in_sizes, int n_in,
                              void* d_out, int out_size) {
    (void)in_sizes; (void)n_in; (void)out_size;
    const float* x           = (const float*)d_in[0];
    const float* temperature = (const float*)d_in[1];
    const float* wqkv        = (const float*)d_in[2];
    const float* wdw         = (const float*)d_in[3];
    const float* wproj       = (const float*)d_in[4];
    float* out = (float*)d_out;

    prep_kernel<<<dim3(12, 32), THREADS>>>(x, wqkv, wdw);
    norm_kernel<<<64, THREADS>>>();
    attn_kernel<<<HEADS * (NTOK / ROWS), THREADS>>>(temperature);
    proj_kernel<<<(128 * 1024) / THREADS, THREADS>>>(wproj, out);
}

// round 8
// speedup vs baseline: 1.0155x; 1.0155x over previous
#include <cuda_runtime.h>

#define HEADS   8
#define NTOK    4096
#define RANK    820        /* # elements strictly below threshold */
#define ROWS    4
#define THREADS 256
#define CAPR    384        /* candidate buffer per row */
#define NREG    12         /* CAPR/32 */

// ---------------- device scratch ----------------
__device__ float  g_qraw[32 * NTOK];      // [head*4+c][n]
__device__ float4 g_kT  [HEADS * NTOK];   // [head][n] -> (c0,c1,c2,c3)
__device__ float4 g_vT  [HEADS * NTOK];
__device__ float  g_qs[32];
__device__ float  g_ks[32];
__device__ float  g_kmean[HEADS * 4];     // per-head k channel means
__device__ float  g_km2[HEADS * 16];      // per-head k second-moment matrix (full 4x4)
__device__ float  g_pre[128 * 1024];      // attention output in proj layout [ch][pixel]

// ---------------- kernel 1: qkv = 1x1x1 group conv + depthwise 3x3 ----------------
__global__ void prep_kernel(const float* __restrict__ x,
                            const float* __restrict__ wqkv,
                            const float* __restrict__ wdw) {
    __shared__ float sh[34][34];
    int o  = blockIdx.x;
    int cd = blockIdx.y;
    int tid = threadIdx.x;
    for (int i = tid; i < 34 * 34; i += THREADS) ((float*)sh)[i] = 0.f;
    __syncthreads();
    float w0 = wqkv[o * 4 + 0], w1 = wqkv[o * 4 + 1];
    float w2 = wqkv[o * 4 + 2], w3 = wqkv[o * 4 + 3];
    for (int p = tid; p < 1024; p += THREADS) {
        int y = p >> 5, xx = p & 31;
        float v = w0 * x[(0 * 32 + cd) * 1024 + p]
                + w1 * x[(1 * 32 + cd) * 1024 + p]
                + w2 * x[(2 * 32 + cd) * 1024 + p]
                + w3 * x[(3 * 32 + cd) * 1024 + p];
        sh[y + 1][xx + 1] = v;
    }
    __syncthreads();
    float k00 = wdw[o*9+0], k01 = wdw[o*9+1], k02 = wdw[o*9+2];
    float k10 = wdw[o*9+3], k11 = wdw[o*9+4], k12 = wdw[o*9+5];
    float k20 = wdw[o*9+6], k21 = wdw[o*9+7], k22 = wdw[o*9+8];
    int g = o >> 2, tt = o & 3;
    int head = cd >> 2, c = cd & 3;
    for (int p = tid; p < 1024; p += THREADS) {
        int y = p >> 5, xx = p & 31;
        float s = k00*sh[y  ][xx] + k01*sh[y  ][xx+1] + k02*sh[y  ][xx+2]
                + k10*sh[y+1][xx] + k11*sh[y+1][xx+1] + k12*sh[y+1][xx+2]
                + k20*sh[y+2][xx] + k21*sh[y+2][xx+1] + k22*sh[y+2][xx+2];
        int n = (p << 2) + tt;
        if (g == 0)      g_qraw[cd * NTOK + n] = s;
        else if (g == 1) ((float*)g_kT)[(head * NTOK + n) * 4 + c] = s;
        else             ((float*)g_vT)[(head * NTOK + n) * 4 + c] = s;
    }
}

// ---------------- kernel 2: norms (blocks 0..63) + per-head k stats (64..71) ----------------
__constant__ int c_pa[10] = {0,0,0,0,1,1,1,2,2,3};
__constant__ int c_pb[10] = {0,1,2,3,1,2,3,2,3,3};

__global__ void norm_kernel() {
    int i = blockIdx.x;
    int tid = threadIdx.x;
    int lane = tid & 31, wid = tid >> 5;
    __shared__ float red[8 * 14];

    if (i < 64) {
        float s = 0.f;
        if (i < 32) {
            const float* q = g_qraw + i * NTOK;
            for (int n = tid; n < NTOK; n += THREADS) { float v = q[n]; s += v * v; }
        } else {
            int j = i - 32; int head = j >> 2, c = j & 3;
            const float* k = ((const float*)g_kT) + head * NTOK * 4 + c;
            for (int n = tid; n < NTOK; n += THREADS) { float v = k[n * 4]; s += v * v; }
        }
        for (int off = 16; off; off >>= 1) s += __shfl_down_sync(0xffffffffu, s, off);
        if (lane == 0) red[wid] = s;
        __syncthreads();
        if (tid == 0) {
            float t = 0.f;
            for (int w = 0; w < 8; w++) t += red[w];
            float scale = 1.f / fmaxf(sqrtf(t), 1e-12f);
            if (i < 32) g_qs[i] = scale; else g_ks[i - 32] = scale;
        }
    } else {
        int head = i - 64;
        const float4* kt = g_kT + head * NTOK;
        float vals[14];
        #pragma unroll
        for (int q = 0; q < 14; q++) vals[q] = 0.f;
        for (int n = tid; n < NTOK; n += THREADS) {
            float4 k = kt[n];
            vals[0] += k.x; vals[1] += k.y; vals[2] += k.z; vals[3] += k.w;
            vals[4]  += k.x*k.x; vals[5]  += k.x*k.y; vals[6]  += k.x*k.z; vals[7] += k.x*k.w;
            vals[8]  += k.y*k.y; vals[9]  += k.y*k.z; vals[10] += k.y*k.w;
            vals[11] += k.z*k.z; vals[12] += k.z*k.w; vals[13] += k.w*k.w;
        }
        #pragma unroll
        for (int q = 0; q < 14; q++)
            for (int off = 16; off; off >>= 1)
                vals[q] += __shfl_down_sync(0xffffffffu, vals[q], off);
        if (lane == 0) {
            #pragma unroll
            for (int q = 0; q < 14; q++) red[wid * 14 + q] = vals[q];
        }
        __syncthreads();
        if (tid < 14) {
            float s = 0.f;
            for (int w = 0; w < 8; w++) s += red[w * 14 + tid];
            s *= (1.f / 4096.f);
            if (tid < 4) g_kmean[head * 4 + tid] = s;
            else {
                int a = c_pa[tid - 4], b = c_pb[tid - 4];
                g_km2[head * 16 + a * 4 + b] = s;
                g_km2[head * 16 + b * 4 + a] = s;
            }
        }
    }
}

// ---------------- kernel 3: fused scores + analytic pivots + exact select + softmax@v ----------------
#define SMEM_SC    (ROWS * NTOK * 4)
#define SMEM_BUF   (ROWS * CAPR * 4)
#define SMEM_BYTES (SMEM_SC + SMEM_BUF)

__device__ __forceinline__ unsigned ordkey(float f) {
    unsigned u = __float_as_uint(f);
    return u ^ (0x80000000u | (unsigned)((int)u >> 31));
}
__device__ __forceinline__ float inv_ordkey(unsigned u) {
    return __uint_as_float(u ^ (0x80000000u | ~(unsigned)((int)u >> 31)));
}
__device__ __forceinline__ unsigned next_pivot(unsigned lo, unsigned hi, int clo, int chi, int useInterp) {
    unsigned span = hi - lo;
    unsigned step;
    if (!useInterp) step = span >> 1;
    else {
        float fr = (float)(RANK + 1 - clo) / (float)(chi - clo);
        step = (unsigned)(fr * (float)span);
        unsigned mn = span >> 4; if (!mn) mn = 1;
        if (step < mn) step = mn;
        if (step > span - mn) step = span - mn;
    }
    if (!step) step = 1;
    return lo + step;
}

__global__ void __launch_bounds__(THREADS, 3) attn_kernel(const float* __restrict__ temperature) {
    extern __shared__ char smem[];
    float*    scf = (float*)smem;                    // ROWS*NTOK score floats
    unsigned* buf = (unsigned*)(smem + SMEM_SC);     // ROWS*CAPR ordkeys
    __shared__ unsigned cnt[4];
    __shared__ unsigned state[4];        // 0=bisect 1=buffer-search 2=done 3=compact-pending
    __shared__ unsigned slo[4], shi[4];
    __shared__ int      sclo[4], schi[4];
    __shared__ unsigned spiv[4], stkey[4], stgt[4], sukey[4];
    __shared__ float    smaxf[4];
    __shared__ int      sany[1];
    __shared__ unsigned gcnt[8];
    __shared__ unsigned wred[96];
    __shared__ float    sred[160];
    __shared__ float    sfin[20];

    int bx   = blockIdx.x;
    int head = bx >> 10;
    int n0   = (bx & 1023) << 2;
    int tid  = threadIdx.x;
    int lane = tid & 31, wid = tid >> 5;

    float temp = temperature[head];
    float4 cf[ROWS];
    #pragma unroll
    for (int r = 0; r < ROWS; r++) {
        int n = n0 + r;
        float a0 = g_qraw[(head*4+0)*NTOK + n] * g_qs[head*4+0] * g_ks[head*4+0] * temp;
        float a1 = g_qraw[(head*4+1)*NTOK + n] * g_qs[head*4+1] * g_ks[head*4+1] * temp;
        float a2 = g_qraw[(head*4+2)*NTOK + n] * g_qs[head*4+2] * g_ks[head*4+2] * temp;
        float a3 = g_qraw[(head*4+3)*NTOK + n] * g_qs[head*4+3] * g_ks[head*4+3] * temp;
        cf[r] = make_float4(a0, a1, a2, a3);
    }

    // ---- analytic per-row pivots from per-head k stats (no score pass needed) ----
    float p1f[ROWS], p5f[ROWS];
    {
        float mu0 = g_kmean[head*4+0], mu1 = g_kmean[head*4+1];
        float mu2 = g_kmean[head*4+2], mu3 = g_kmean[head*4+3];
        const float* M = g_km2 + head * 16;
        float m00=M[0], m01=M[1], m02=M[2], m03=M[3];
        float m11=M[5], m12=M[6], m13=M[7];
        float m22=M[10], m23=M[11], m33=M[15];
        #pragma unroll
        for (int r = 0; r < ROWS; r++) {
            float cx = cf[r].x, cy = cf[r].y, cz = cf[r].z, cw = cf[r].w;
            float mean = cx*mu0 + cy*mu1 + cz*mu2 + cw*mu3;
            float t0 = m00*cx + m01*cy + m02*cz + m03*cw;
            float t1 = m01*cx + m11*cy + m12*cz + m13*cw;
            float t2 = m02*cx + m12*cy + m22*cz + m23*cw;
            float t3 = m03*cx + m13*cy + m23*cz + m33*cw;
            float es2 = cx*t0 + cy*t1 + cz*t2 + cw*t3;
            float var = es2 - mean * mean;
            float sig = sqrtf(fmaxf(var, 0.f));
            p1f[r] = fmaf(-0.9741f, sig, mean);   // quantile ~0.165
            p5f[r] = fmaf(-0.7225f, sig, mean);   // quantile ~0.235
        }
    }
    if (tid < 4) cnt[tid] = 0;
    __syncthreads();

    // ---- pass 1: scores -> smem floats; count below pivots + compact window in flight ----
    float fmax_[ROWS] = {-3.4e38f, -3.4e38f, -3.4e38f, -3.4e38f};
    int c1t[ROWS] = {0,0,0,0}, cwt[ROWS] = {0,0,0,0};
    const float4* kt = g_kT + head * NTOK;
    #pragma unroll
    for (int jo = 0; jo < 4; jo++) {
        int mb = (jo << 10) + (tid << 2);
        float4 k0 = __ldg(&kt[mb+0]);
        float4 k1 = __ldg(&kt[mb+1]);
        float4 k2 = __ldg(&kt[mb+2]);
        float4 k3 = __ldg(&kt[mb+3]);
        #pragma unroll
        for (int r = 0; r < ROWS; r++) {
            float s0 = fmaf(cf[r].x,k0.x, fmaf(cf[r].y,k0.y, fmaf(cf[r].z,k0.z, cf[r].w*k0.w)));
            float s1 = fmaf(cf[r].x,k1.x, fmaf(cf[r].y,k1.y, fmaf(cf[r].z,k1.z, cf[r].w*k1.w)));
            float s2 = fmaf(cf[r].x,k2.x, fmaf(cf[r].y,k2.y, fmaf(cf[r].z,k2.z, cf[r].w*k2.w)));
            float s3 = fmaf(cf[r].x,k3.x, fmaf(cf[r].y,k3.y, fmaf(cf[r].z,k3.z, cf[r].w*k3.w)));
            *(float4*)(scf + r * NTOK + mb) = make_float4(s0, s1, s2, s3);
            fmax_[r] = fmaxf(fmax_[r], fmaxf(fmaxf(s0,s1), fmaxf(s2,s3)));
            float p1 = p1f[r], p5 = p5f[r];
            c1t[r] += (s0 < p1) + (s1 < p1) + (s2 < p1) + (s3 < p1);
            int wx = (s0 >= p1) & (s0 < p5);
            int wy = (s1 >= p1) & (s1 < p5);
            int wz = (s2 >= p1) & (s2 < p5);
            int ww = (s3 >= p1) & (s3 < p5);
            int nc = wx + wy + wz + ww;
            cwt[r] += nc;
            unsigned bal = __ballot_sync(0xffffffffu, nc != 0);
            if (bal) {
                int incl = nc;
                #pragma unroll
                for (int d = 1; d < 32; d <<= 1) {
                    int v = __shfl_up_sync(0xffffffffu, incl, d);
                    if (lane >= d) incl += v;
                }
                unsigned base = 0;
                if (lane == 31) base = atomicAdd(&cnt[r], (unsigned)incl);
                base = __shfl_sync(0xffffffffu, base, 31);
                unsigned p = base + (unsigned)(incl - nc);
                if (p + (unsigned)nc <= CAPR) {
                    if (wx) buf[r * CAPR + p++] = ordkey(s0);
                    if (wy) buf[r * CAPR + p++] = ordkey(s1);
                    if (wz) buf[r * CAPR + p++] = ordkey(s2);
                    if (ww) buf[r * CAPR + p++] = ordkey(s3);
                }
            }
        }
    }
    // block-reduce max + counts
    #pragma unroll
    for (int r = 0; r < ROWS; r++) {
        for (int off = 16; off; off >>= 1)
            fmax_[r] = fmaxf(fmax_[r], __shfl_xor_sync(0xffffffffu, fmax_[r], off));
        c1t[r] = __reduce_add_sync(0xffffffffu, c1t[r]);
        cwt[r] = __reduce_add_sync(0xffffffffu, cwt[r]);
    }
    if (lane == 0) {
        #pragma unroll
        for (int r = 0; r < ROWS; r++) {
            wred[wid*12 + r]     = __float_as_uint(fmax_[r]);
            wred[wid*12 + 4 + r] = (unsigned)c1t[r];
            wred[wid*12 + 8 + r] = (unsigned)(c1t[r] + cwt[r]);
        }
    }
    __syncthreads();
    if (tid < 12) {
        int r = tid & 3, kind = tid >> 2;
        if (kind == 0) {
            float v = -3.4e38f;
            for (int w = 0; w < 8; w++) v = fmaxf(v, __uint_as_float(wred[w*12 + r]));
            sukey[r] = ordkey(v); smaxf[r] = v;
        } else {
            unsigned s = 0;
            for (int w = 0; w < 8; w++) s += wred[w*12 + kind*4 + r];
            gcnt[(kind-1)*4 + r] = s;
        }
    }
    __syncthreads();

    // ---- classify rows ----
    if (tid < 4) {
        int c1v = (int)gcnt[tid], c5v = (int)gcnt[4 + tid];
        unsigned p1 = ordkey(p1f[tid]), p5 = ordkey(p5f[tid]);
        if (c1v <= RANK && RANK < c5v && (c5v - c1v) <= CAPR) {
            state[tid] = 1; slo[tid] = p1; shi[tid] = p5; stgt[tid] = (unsigned)(RANK - c1v);
        } else {
            unsigned lo, hi; int clo, chi;
            if (RANK < c1v)      { lo = 0u; hi = p1; clo = 0;   chi = c1v; }
            else if (RANK < c5v) { lo = p1; hi = p5; clo = c1v; chi = c5v; }
            else                 { lo = p5; hi = sukey[tid] + 1u; clo = c5v; chi = NTOK; }
            slo[tid] = lo; shi[tid] = hi; sclo[tid] = clo; schi[tid] = chi;
            if (hi - lo <= 1u)            { stkey[tid] = lo; state[tid] = 2; }
            else if (chi - clo <= CAPR)   { state[tid] = 3; }
            else { state[tid] = 0; spiv[tid] = next_pivot(lo, hi, clo, chi, 1); }
        }
    }

    // ---- fallback bisect loop (rare) ----
    for (int iter = 0; iter < 72; iter++) {
        __syncthreads();
        if (tid == 0)
            sany[0] = (state[0]==0) | (state[1]==0) | (state[2]==0) | (state[3]==0);
        __syncthreads();
        if (!sany[0]) break;
        float pvf[ROWS]; int act[ROWS];
        #pragma unroll
        for (int r = 0; r < ROWS; r++) { act[r] = (state[r] == 0); pvf[r] = inv_ordkey(spiv[r]); }
        int cr[ROWS] = {0,0,0,0};
        #pragma unroll 1
        for (int jo = 0; jo < 4; jo++) {
            int mb = (jo << 10) + (tid << 2);
            #pragma unroll
            for (int r = 0; r < ROWS; r++) {
                if (act[r]) {
                    float4 ss = *(const float4*)(scf + r * NTOK + mb);
                    cr[r] += (ss.x < pvf[r]) + (ss.y < pvf[r]) + (ss.z < pvf[r]) + (ss.w < pvf[r]);
                }
            }
        }
        #pragma unroll
        for (int r = 0; r < ROWS; r++) cr[r] = __reduce_add_sync(0xffffffffu, cr[r]);
        if (lane == 0) {
            #pragma unroll
            for (int r = 0; r < ROWS; r++) wred[wid*4 + r] = (unsigned)cr[r];
        }
        __syncthreads();
        if (tid < 4 && state[tid] == 0) {
            int tot = 0;
            for (int w = 0; w < 8; w++) tot += (int)wred[w*4 + tid];
            if (tot <= RANK) { slo[tid] = spiv[tid]; sclo[tid] = tot; }
            else             { shi[tid] = spiv[tid]; schi[tid] = tot; }
            unsigned lo = slo[tid], hi = shi[tid];
            int cc = schi[tid] - sclo[tid];
            if (hi - lo <= 1u)      { stkey[tid] = lo; state[tid] = 2; }
            else if (cc <= CAPR)    { state[tid] = 3; }
            else spiv[tid] = next_pivot(lo, hi, sclo[tid], schi[tid], !(iter & 1));
        }
    }
    __syncthreads();
    if (tid < 4) {
        if (state[tid] == 0) { stkey[tid] = slo[tid]; state[tid] = 2; } // safety
        if (state[tid] == 3) cnt[tid] = 0;
    }
    __syncthreads();

    // ---- fallback compaction (rows in state 3) ----
    {
        bool anyc = (state[0]==3) | (state[1]==3) | (state[2]==3) | (state[3]==3);
        if (anyc) {
            #pragma unroll 1
            for (int r = 0; r < ROWS; r++) {
                if (state[r] == 3) {
                    float lof = inv_ordkey(slo[r]);
                    float hif = inv_ordkey(shi[r]);
                    #pragma unroll 1
                    for (int jo = 0; jo < 4; jo++) {
                        int mb = (jo << 10) + (tid << 2);
                        float4 ss = *(const float4*)(scf + r * NTOK + mb);
                        int wx = (ss.x >= lof) & (ss.x < hif);
                        int wy = (ss.y >= lof) & (ss.y < hif);
                        int wz = (ss.z >= lof) & (ss.z < hif);
                        int ww = (ss.w >= lof) & (ss.w < hif);
                        int nc = wx + wy + wz + ww;
                        if (nc) {
                            unsigned bs = atomicAdd(&cnt[r], (unsigned)nc);
                            if (bs + (unsigned)nc <= CAPR) {
                                unsigned p = bs;
                                if (wx) buf[r * CAPR + p++] = ordkey(ss.x);
                                if (wy) buf[r * CAPR + p++] = ordkey(ss.y);
                                if (wz) buf[r * CAPR + p++] = ordkey(ss.z);
                                if (ww) buf[r * CAPR + p++] = ordkey(ss.w);
                            }
                        }
                    }
                }
            }
            __syncthreads();
            if (tid < 4 && state[tid] == 3) {
                stgt[tid] = (unsigned)(RANK - sclo[tid]);
                state[tid] = 1;
            }
            __syncthreads();
        }
    }

    // ---- warp-register bisect over candidate buffer (1 warp / row) ----
    if (wid < 4 && state[wid] == 1) {
        int c = (int)cnt[wid]; if (c > CAPR) c = CAPR;
        unsigned cand[NREG];
        #pragma unroll
        for (int i = 0; i < NREG; i++) {
            int idx = i * 32 + lane;
            cand[i] = (idx < c) ? buf[wid * CAPR + idx] : 0xFFFFFFFFu;
        }
        unsigned lo = slo[wid], hi = shi[wid], tgt = stgt[wid];
        while (hi - lo > 1u) {
            unsigned mid = lo + ((hi - lo) >> 1);
            unsigned cb = 0;
            #pragma unroll
            for (int i = 0; i < NREG; i++) cb += (cand[i] < mid);
            cb = __reduce_add_sync(0xffffffffu, cb);
            if (cb <= tgt) lo = mid; else hi = mid;
        }
        if (lane == 0) stkey[wid] = lo;
    }
    __syncthreads();

    // ---- pass 2: masked softmax + p@v ----
    float thrf[ROWS], mrow[ROWS];
    #pragma unroll
    for (int r = 0; r < ROWS; r++) { thrf[r] = inv_ordkey(stkey[r]); mrow[r] = smaxf[r]; }
    float zz[ROWS] = {0.f, 0.f, 0.f, 0.f};
    float4 acc[ROWS];
    #pragma unroll
    for (int r = 0; r < ROWS; r++) acc[r] = make_float4(0.f, 0.f, 0.f, 0.f);
    const float4* vt = g_vT + head * NTOK;
    #pragma unroll
    for (int jo = 0; jo < 4; jo++) {
        int mb = (jo << 10) + (tid << 2);
        float4 v0 = __ldg(&vt[mb+0]);
        float4 v1 = __ldg(&vt[mb+1]);
        float4 v2 = __ldg(&vt[mb+2]);
        float4 v3 = __ldg(&vt[mb+3]);
        #pragma unroll
        for (int r = 0; r < ROWS; r++) {
            float4 ss = *(const float4*)(scf + r * NTOK + mb);
            float w0 = (ss.x >= thrf[r]) ? __expf(ss.x - mrow[r]) : 0.f;
            float w1 = (ss.y >= thrf[r]) ? __expf(ss.y - mrow[r]) : 0.f;
            float w2 = (ss.z >= thrf[r]) ? __expf(ss.z - mrow[r]) : 0.f;
            float w3 = (ss.w >= thrf[r]) ? __expf(ss.w - mrow[r]) : 0.f;
            zz[r] += ((w0 + w1) + (w2 + w3));
            acc[r].x += w0*v0.x + w1*v1.x + w2*v2.x + w3*v3.x;
            acc[r].y += w0*v0.y + w1*v1.y + w2*v2.y + w3*v3.y;
            acc[r].z += w0*v0.z + w1*v1.z + w2*v2.z + w3*v3.z;
            acc[r].w += w0*v0.w + w1*v1.w + w2*v2.w + w3*v3.w;
        }
    }

    // block-reduce 20 accumulators
    float vals[20];
    #pragma unroll
    for (int r = 0; r < ROWS; r++) {
        vals[r*5 + 0] = zz[r];
        vals[r*5 + 1] = acc[r].x; vals[r*5 + 2] = acc[r].y;
        vals[r*5 + 3] = acc[r].z; vals[r*5 + 4] = acc[r].w;
    }
    #pragma unroll
    for (int q = 0; q < 20; q++)
        for (int off = 16; off; off >>= 1)
            vals[q] += __shfl_down_sync(0xffffffffu, vals[q], off);
    if (lane == 0) {
        #pragma unroll
        for (int q = 0; q < 20; q++) sred[q*8 + wid] = vals[q];
    }
    __syncthreads();
    if (tid < 20) {
        float s = 0.f;
        for (int w = 0; w < 8; w++) s += sred[tid*8 + w];
        sfin[tid] = s;
    }
    __syncthreads();
    if (tid < 16) {
        int r = tid >> 2, c = tid & 3;
        float val = sfin[r*5 + 1 + c] / sfin[r*5 + 0];
        int n = n0 + r;
        int tt = n & 3, pixel = n >> 2;
        int ch = tt * 32 + head * 4 + c;
        g_pre[ch * 1024 + pixel] = val;
    }
}

// ---------------- kernel 4: final 1x1 projection ----------------
__global__ void proj_kernel(const float* __restrict__ wproj, float* __restrict__ out) {
    int idx = blockIdx.x * THREADS + threadIdx.x;
    int o = idx >> 10, p = idx & 1023;
    const float* w = wproj + o * 128;
    float s = 0.f;
    #pragma unroll 8
    for (int ch = 0; ch < 128; ch++) s += w[ch] * g_pre[ch * 1024 + p];
    out[idx] = s;
}

// ---------------- launch ----------------
extern "C" void kernel_launch(void* const* d_in, const int* in_sizes, int n_in,
                              void* d_out, int out_size) {
    (void)in_sizes; (void)n_in; (void)out_size;
    const float* x           = (const float*)d_in[0];
    const float* temperature = (const float*)d_in[1];
    const float* wqkv        = (const float*)d_in[2];
    const float* wdw         = (const float*)d_in[3];
    const float* wproj       = (const float*)d_in[4];
    float* out = (float*)d_out;

    cudaFuncSetAttribute(attn_kernel, cudaFuncAttributeMaxDynamicSharedMemorySize, SMEM_BYTES);

    prep_kernel<<<dim3(12, 32), THREADS>>>(x, wqkv, wdw);
    norm_kernel<<<72, THREADS>>>();
    attn_kernel<<<HEADS * (NTOK / ROWS), THREADS, SMEM_BYTES>>>(temperature);
    proj_kernel<<<(128 * 1024) / THREADS, THREADS>>>(wproj, out);
}

// round 9
// speedup vs baseline: 1.1270x; 1.1098x over previous
#include <cuda_runtime.h>

#define HEADS   8
#define NTOK    4096
#define RANK    820        /* # elements strictly below threshold */
#define ROWS    4
#define THREADS 256
#define CAPR    384        /* candidate buffer per row */
#define NREG    12         /* CAPR/32 */

// ---------------- device scratch ----------------
__device__ float  g_qraw[32 * NTOK];      // [head*4+c][n]
__device__ float4 g_kT  [HEADS * NTOK];   // [head][n] -> (c0,c1,c2,c3)
__device__ float4 g_vT  [HEADS * NTOK];
__device__ float  g_qs[32];
__device__ float  g_ks[32];
__device__ float  g_kmean[HEADS * 4];     // per-head k channel means
__device__ float  g_km2[HEADS * 16];      // per-head k second-moment matrix (full 4x4)
__device__ float  g_pre[128 * 1024];      // attention output in proj layout [ch][pixel]

// ---------------- kernel 1: qkv = 1x1x1 group conv + depthwise 3x3 ----------------
__global__ void prep_kernel(const float* __restrict__ x,
                            const float* __restrict__ wqkv,
                            const float* __restrict__ wdw) {
    __shared__ float sh[34][34];
    int o  = blockIdx.x;
    int cd = blockIdx.y;
    int tid = threadIdx.x;
    for (int i = tid; i < 34 * 34; i += THREADS) ((float*)sh)[i] = 0.f;
    __syncthreads();
    float w0 = wqkv[o * 4 + 0], w1 = wqkv[o * 4 + 1];
    float w2 = wqkv[o * 4 + 2], w3 = wqkv[o * 4 + 3];
    for (int p = tid; p < 1024; p += THREADS) {
        int y = p >> 5, xx = p & 31;
        float v = w0 * x[(0 * 32 + cd) * 1024 + p]
                + w1 * x[(1 * 32 + cd) * 1024 + p]
                + w2 * x[(2 * 32 + cd) * 1024 + p]
                + w3 * x[(3 * 32 + cd) * 1024 + p];
        sh[y + 1][xx + 1] = v;
    }
    __syncthreads();
    float k00 = wdw[o*9+0], k01 = wdw[o*9+1], k02 = wdw[o*9+2];
    float k10 = wdw[o*9+3], k11 = wdw[o*9+4], k12 = wdw[o*9+5];
    float k20 = wdw[o*9+6], k21 = wdw[o*9+7], k22 = wdw[o*9+8];
    int g = o >> 2, tt = o & 3;
    int head = cd >> 2, c = cd & 3;
    for (int p = tid; p < 1024; p += THREADS) {
        int y = p >> 5, xx = p & 31;
        float s = k00*sh[y  ][xx] + k01*sh[y  ][xx+1] + k02*sh[y  ][xx+2]
                + k10*sh[y+1][xx] + k11*sh[y+1][xx+1] + k12*sh[y+1][xx+2]
                + k20*sh[y+2][xx] + k21*sh[y+2][xx+1] + k22*sh[y+2][xx+2];
        int n = (p << 2) + tt;
        if (g == 0)      g_qraw[cd * NTOK + n] = s;
        else if (g == 1) ((float*)g_kT)[(head * NTOK + n) * 4 + c] = s;
        else             ((float*)g_vT)[(head * NTOK + n) * 4 + c] = s;
    }
}

// ---------------- kernel 2: norms (blocks 0..63) + per-head k stats (64..71) ----------------
__constant__ int c_pa[10] = {0,0,0,0,1,1,1,2,2,3};
__constant__ int c_pb[10] = {0,1,2,3,1,2,3,2,3,3};

__global__ void norm_kernel() {
    int i = blockIdx.x;
    int tid = threadIdx.x;
    int lane = tid & 31, wid = tid >> 5;
    __shared__ float red[8 * 14];

    if (i < 64) {
        float s = 0.f;
        if (i < 32) {
            const float* q = g_qraw + i * NTOK;
            for (int n = tid; n < NTOK; n += THREADS) { float v = q[n]; s += v * v; }
        } else {
            int j = i - 32; int head = j >> 2, c = j & 3;
            const float* k = ((const float*)g_kT) + head * NTOK * 4 + c;
            for (int n = tid; n < NTOK; n += THREADS) { float v = k[n * 4]; s += v * v; }
        }
        for (int off = 16; off; off >>= 1) s += __shfl_down_sync(0xffffffffu, s, off);
        if (lane == 0) red[wid] = s;
        __syncthreads();
        if (tid == 0) {
            float t = 0.f;
            for (int w = 0; w < 8; w++) t += red[w];
            float scale = 1.f / fmaxf(sqrtf(t), 1e-12f);
            if (i < 32) g_qs[i] = scale; else g_ks[i - 32] = scale;
        }
    } else {
        int head = i - 64;
        const float4* kt = g_kT + head * NTOK;
        float vals[14];
        #pragma unroll
        for (int q = 0; q < 14; q++) vals[q] = 0.f;
        for (int n = tid; n < NTOK; n += THREADS) {
            float4 k = kt[n];
            vals[0] += k.x; vals[1] += k.y; vals[2] += k.z; vals[3] += k.w;
            vals[4]  += k.x*k.x; vals[5]  += k.x*k.y; vals[6]  += k.x*k.z; vals[7] += k.x*k.w;
            vals[8]  += k.y*k.y; vals[9]  += k.y*k.z; vals[10] += k.y*k.w;
            vals[11] += k.z*k.z; vals[12] += k.z*k.w; vals[13] += k.w*k.w;
        }
        #pragma unroll
        for (int q = 0; q < 14; q++)
            for (int off = 16; off; off >>= 1)
                vals[q] += __shfl_down_sync(0xffffffffu, vals[q], off);
        if (lane == 0) {
            #pragma unroll
            for (int q = 0; q < 14; q++) red[wid * 14 + q] = vals[q];
        }
        __syncthreads();
        if (tid < 14) {
            float s = 0.f;
            for (int w = 0; w < 8; w++) s += red[w * 14 + tid];
            s *= (1.f / 4096.f);
            if (tid < 4) g_kmean[head * 4 + tid] = s;
            else {
                int a = c_pa[tid - 4], b = c_pb[tid - 4];
                g_km2[head * 16 + a * 4 + b] = s;
                g_km2[head * 16 + b * 4 + a] = s;
            }
        }
    }
}

// ---------------- kernel 3 ----------------
#define SMEM_SC    (ROWS * NTOK * 4)
#define SMEM_BUF   (ROWS * CAPR * 4)
#define SMEM_BYTES (SMEM_SC + SMEM_BUF)

__device__ __forceinline__ unsigned ordkey(float f) {
    unsigned u = __float_as_uint(f);
    return u ^ (0x80000000u | (unsigned)((int)u >> 31));
}
__device__ __forceinline__ float inv_ordkey(unsigned u) {
    return __uint_as_float(u ^ (0x80000000u | ~(unsigned)((int)u >> 31)));
}
__device__ __forceinline__ unsigned next_pivot(unsigned lo, unsigned hi, int clo, int chi, int useInterp) {
    unsigned span = hi - lo;
    unsigned step;
    if (!useInterp) step = span >> 1;
    else {
        float fr = (float)(RANK + 1 - clo) / (float)(chi - clo);
        step = (unsigned)(fr * (float)span);
        unsigned mn = span >> 4; if (!mn) mn = 1;
        if (step < mn) step = mn;
        if (step > span - mn) step = span - mn;
    }
    if (!step) step = 1;
    return lo + step;
}

__global__ void __launch_bounds__(THREADS, 3) attn_kernel(const float* __restrict__ temperature) {
    extern __shared__ char smem[];
    float*    scf = (float*)smem;                    // ROWS*NTOK score floats
    unsigned* buf = (unsigned*)(smem + SMEM_SC);     // ROWS*CAPR ordkeys
    __shared__ unsigned cnt[4];
    __shared__ unsigned state[4];        // 0=bisect 1=buffer-search 2=done 3=compact-pending
    __shared__ unsigned slo[4], shi[4];
    __shared__ int      sclo[4], schi[4];
    __shared__ unsigned spiv[4], stkey[4], stgt[4];
    __shared__ int      sany[1];
    __shared__ unsigned gcnt[8];
    __shared__ unsigned wred[64];
    __shared__ float    sred[160];
    __shared__ float    sfin[20];

    int bx   = blockIdx.x;
    int head = bx >> 10;
    int n0   = (bx & 1023) << 2;
    int tid  = threadIdx.x;
    int lane = tid & 31, wid = tid >> 5;

    float temp = temperature[head];
    float4 cf[ROWS];
    float  Mr[ROWS];     // analytic stabilizer: M = sum |a_c| >= max score (Cauchy-Schwarz)
    #pragma unroll
    for (int r = 0; r < ROWS; r++) {
        int n = n0 + r;
        float a0 = g_qraw[(head*4+0)*NTOK + n] * g_qs[head*4+0] * g_ks[head*4+0] * temp;
        float a1 = g_qraw[(head*4+1)*NTOK + n] * g_qs[head*4+1] * g_ks[head*4+1] * temp;
        float a2 = g_qraw[(head*4+2)*NTOK + n] * g_qs[head*4+2] * g_ks[head*4+2] * temp;
        float a3 = g_qraw[(head*4+3)*NTOK + n] * g_qs[head*4+3] * g_ks[head*4+3] * temp;
        cf[r] = make_float4(a0, a1, a2, a3);
        Mr[r] = fabsf(a0) + fabsf(a1) + fabsf(a2) + fabsf(a3);
    }

    // ---- analytic per-row pivots from per-head k stats ----
    float p1f[ROWS], p5f[ROWS];
    {
        float mu0 = g_kmean[head*4+0], mu1 = g_kmean[head*4+1];
        float mu2 = g_kmean[head*4+2], mu3 = g_kmean[head*4+3];
        const float* M = g_km2 + head * 16;
        float m00=M[0], m01=M[1], m02=M[2], m03=M[3];
        float m11=M[5], m12=M[6], m13=M[7];
        float m22=M[10], m23=M[11], m33=M[15];
        #pragma unroll
        for (int r = 0; r < ROWS; r++) {
            float cx = cf[r].x, cy = cf[r].y, cz = cf[r].z, cw = cf[r].w;
            float mean = cx*mu0 + cy*mu1 + cz*mu2 + cw*mu3;
            float t0 = m00*cx + m01*cy + m02*cz + m03*cw;
            float t1 = m01*cx + m11*cy + m12*cz + m13*cw;
            float t2 = m02*cx + m12*cy + m22*cz + m23*cw;
            float t3 = m03*cx + m13*cy + m23*cz + m33*cw;
            float es2 = cx*t0 + cy*t1 + cz*t2 + cw*t3;
            float var = es2 - mean * mean;
            float sig = sqrtf(fmaxf(var, 0.f));
            p1f[r] = fmaf(-0.9741f, sig, mean);   // quantile ~0.165
            p5f[r] = fmaf(-0.7225f, sig, mean);   // quantile ~0.235
        }
    }
    if (tid < 4) cnt[tid] = 0;
    __syncthreads();

    // ---- pass 1: scores -> smem; count below pivots + compact window (simple atomics) ----
    int c1t[ROWS] = {0,0,0,0}, cwt[ROWS] = {0,0,0,0};
    const float4* kt = g_kT + head * NTOK;
    #pragma unroll
    for (int jo = 0; jo < 4; jo++) {
        int mb = (jo << 10) + (tid << 2);
        float4 k0 = __ldg(&kt[mb+0]);
        float4 k1 = __ldg(&kt[mb+1]);
        float4 k2 = __ldg(&kt[mb+2]);
        float4 k3 = __ldg(&kt[mb+3]);
        #pragma unroll
        for (int r = 0; r < ROWS; r++) {
            float s0 = fmaf(cf[r].x,k0.x, fmaf(cf[r].y,k0.y, fmaf(cf[r].z,k0.z, cf[r].w*k0.w)));
            float s1 = fmaf(cf[r].x,k1.x, fmaf(cf[r].y,k1.y, fmaf(cf[r].z,k1.z, cf[r].w*k1.w)));
            float s2 = fmaf(cf[r].x,k2.x, fmaf(cf[r].y,k2.y, fmaf(cf[r].z,k2.z, cf[r].w*k2.w)));
            float s3 = fmaf(cf[r].x,k3.x, fmaf(cf[r].y,k3.y, fmaf(cf[r].z,k3.z, cf[r].w*k3.w)));
            *(float4*)(scf + r * NTOK + mb) = make_float4(s0, s1, s2, s3);
            float p1 = p1f[r], p5 = p5f[r];
            c1t[r] += (s0 < p1) + (s1 < p1) + (s2 < p1) + (s3 < p1);
            int wx = (s0 >= p1) & (s0 < p5);
            int wy = (s1 >= p1) & (s1 < p5);
            int wz = (s2 >= p1) & (s2 < p5);
            int ww = (s3 >= p1) & (s3 < p5);
            int nc = wx + wy + wz + ww;
            if (nc) {
                cwt[r] += nc;
                unsigned bs = atomicAdd(&cnt[r], (unsigned)nc);
                if (bs + (unsigned)nc <= CAPR) {
                    unsigned p = bs;
                    if (wx) buf[r * CAPR + p++] = ordkey(s0);
                    if (wy) buf[r * CAPR + p++] = ordkey(s1);
                    if (wz) buf[r * CAPR + p++] = ordkey(s2);
                    if (ww) buf[r * CAPR + p++] = ordkey(s3);
                }
            }
        }
    }
    // block-reduce counts only
    #pragma unroll
    for (int r = 0; r < ROWS; r++) {
        c1t[r] = __reduce_add_sync(0xffffffffu, c1t[r]);
        cwt[r] = __reduce_add_sync(0xffffffffu, cwt[r]);
    }
    if (lane == 0) {
        #pragma unroll
        for (int r = 0; r < ROWS; r++) {
            wred[wid*8 + r]     = (unsigned)c1t[r];
            wred[wid*8 + 4 + r] = (unsigned)(c1t[r] + cwt[r]);
        }
    }
    __syncthreads();
    if (tid < 8) {
        unsigned s = 0;
        for (int w = 0; w < 8; w++) s += wred[w*8 + tid];
        gcnt[tid] = s;
    }
    __syncthreads();

    // ---- classify rows ----
    if (tid < 4) {
        int c1v = (int)gcnt[tid], c5v = (int)gcnt[4 + tid];
        unsigned p1 = ordkey(p1f[tid]), p5 = ordkey(p5f[tid]);
        float Mv = (tid == 0) ? Mr[0] : (tid == 1) ? Mr[1] : (tid == 2) ? Mr[2] : Mr[3];
        if (c1v <= RANK && RANK < c5v && (c5v - c1v) <= CAPR) {
            state[tid] = 1; slo[tid] = p1; shi[tid] = p5; stgt[tid] = (unsigned)(RANK - c1v);
        } else {
            unsigned lo, hi; int clo, chi;
            if (RANK < c1v)      { lo = 0u; hi = p1; clo = 0;   chi = c1v; }
            else if (RANK < c5v) { lo = p1; hi = p5; clo = c1v; chi = c5v; }
            else                 { lo = p5; hi = ordkey(Mv) + 1u; clo = c5v; chi = NTOK; }
            slo[tid] = lo; shi[tid] = hi; sclo[tid] = clo; schi[tid] = chi;
            if (hi - lo <= 1u)            { stkey[tid] = lo; state[tid] = 2; }
            else if (chi - clo <= CAPR)   { state[tid] = 3; }
            else { state[tid] = 0; spiv[tid] = next_pivot(lo, hi, clo, chi, 1); }
        }
    }

    // ---- fallback bisect loop (rare) ----
    for (int iter = 0; iter < 72; iter++) {
        __syncthreads();
        if (tid == 0)
            sany[0] = (state[0]==0) | (state[1]==0) | (state[2]==0) | (state[3]==0);
        __syncthreads();
        if (!sany[0]) break;
        float pvf[ROWS]; int act[ROWS];
        #pragma unroll
        for (int r = 0; r < ROWS; r++) { act[r] = (state[r] == 0); pvf[r] = inv_ordkey(spiv[r]); }
        int cr[ROWS] = {0,0,0,0};
        #pragma unroll 1
        for (int jo = 0; jo < 4; jo++) {
            int mb = (jo << 10) + (tid << 2);
            #pragma unroll
            for (int r = 0; r < ROWS; r++) {
                if (act[r]) {
                    float4 ss = *(const float4*)(scf + r * NTOK + mb);
                    cr[r] += (ss.x < pvf[r]) + (ss.y < pvf[r]) + (ss.z < pvf[r]) + (ss.w < pvf[r]);
                }
            }
        }
        #pragma unroll
        for (int r = 0; r < ROWS; r++) cr[r] = __reduce_add_sync(0xffffffffu, cr[r]);
        if (lane == 0) {
            #pragma unroll
            for (int r = 0; r < ROWS; r++) wred[wid*4 + r] = (unsigned)cr[r];
        }
        __syncthreads();
        if (tid < 4 && state[tid] == 0) {
            int tot = 0;
            for (int w = 0; w < 8; w++) tot += (int)wred[w*4 + tid];
            if (tot <= RANK) { slo[tid] = spiv[tid]; sclo[tid] = tot; }
            else             { shi[tid] = spiv[tid]; schi[tid] = tot; }
            unsigned lo = slo[tid], hi = shi[tid];
            int cc = schi[tid] - sclo[tid];
            if (hi - lo <= 1u)      { stkey[tid] = lo; state[tid] = 2; }
            else if (cc <= CAPR)    { state[tid] = 3; }
            else spiv[tid] = next_pivot(lo, hi, sclo[tid], schi[tid], !(iter & 1));
        }
    }
    __syncthreads();
    if (tid < 4) {
        if (state[tid] == 0) { stkey[tid] = slo[tid]; state[tid] = 2; } // safety
        if (state[tid] == 3) cnt[tid] = 0;
    }
    __syncthreads();

    // ---- fallback compaction (rows in state 3) ----
    {
        bool anyc = (state[0]==3) | (state[1]==3) | (state[2]==3) | (state[3]==3);
        if (anyc) {
            #pragma unroll 1
            for (int r = 0; r < ROWS; r++) {
                if (state[r] == 3) {
                    float lof = inv_ordkey(slo[r]);
                    float hif = inv_ordkey(shi[r]);
                    #pragma unroll 1
                    for (int jo = 0; jo < 4; jo++) {
                        int mb = (jo << 10) + (tid << 2);
                        float4 ss = *(const float4*)(scf + r * NTOK + mb);
                        int wx = (ss.x >= lof) & (ss.x < hif);
                        int wy = (ss.y >= lof) & (ss.y < hif);
                        int wz = (ss.z >= lof) & (ss.z < hif);
                        int ww = (ss.w >= lof) & (ss.w < hif);
                        int nc = wx + wy + wz + ww;
                        if (nc) {
                            unsigned bs = atomicAdd(&cnt[r], (unsigned)nc);
                            if (bs + (unsigned)nc <= CAPR) {
                                unsigned p = bs;
                                if (wx) buf[r * CAPR + p++] = ordkey(ss.x);
                                if (wy) buf[r * CAPR + p++] = ordkey(ss.y);
                                if (wz) buf[r * CAPR + p++] = ordkey(ss.z);
                                if (ww) buf[r * CAPR + p++] = ordkey(ss.w);
                            }
                        }
                    }
                }
            }
            __syncthreads();
            if (tid < 4 && state[tid] == 3) {
                stgt[tid] = (unsigned)(RANK - sclo[tid]);
                state[tid] = 1;
            }
            __syncthreads();
        }
    }

    // ---- warp-register bisect over candidate buffer (1 warp / row) ----
    if (wid < 4 && state[wid] == 1) {
        int c = (int)cnt[wid]; if (c > CAPR) c = CAPR;
        unsigned cand[NREG];
        #pragma unroll
        for (int i = 0; i < NREG; i++) {
            int idx = i * 32 + lane;
            cand[i] = (idx < c) ? buf[wid * CAPR + idx] : 0xFFFFFFFFu;
        }
        unsigned lo = slo[wid], hi = shi[wid], tgt = stgt[wid];
        while (hi - lo > 1u) {
            unsigned mid = lo + ((hi - lo) >> 1);
            unsigned cb = 0;
            #pragma unroll
            for (int i = 0; i < NREG; i++) cb += (cand[i] < mid);
            cb = __reduce_add_sync(0xffffffffu, cb);
            if (cb <= tgt) lo = mid; else hi = mid;
        }
        if (lane == 0) stkey[wid] = lo;
    }
    __syncthreads();

    // ---- pass 2: masked softmax + p@v (stabilized by analytic bound M) ----
    float thrf[ROWS];
    #pragma unroll
    for (int r = 0; r < ROWS; r++) thrf[r] = inv_ordkey(stkey[r]);
    float zz[ROWS] = {0.f, 0.f, 0.f, 0.f};
    float4 acc[ROWS];
    #pragma unroll
    for (int r = 0; r < ROWS; r++) acc[r] = make_float4(0.f, 0.f, 0.f, 0.f);
    const float4* vt = g_vT + head * NTOK;
    #pragma unroll
    for (int jo = 0; jo < 4; jo++) {
        int mb = (jo << 10) + (tid << 2);
        float4 v0 = __ldg(&vt[mb+0]);
        float4 v1 = __ldg(&vt[mb+1]);
        float4 v2 = __ldg(&vt[mb+2]);
        float4 v3 = __ldg(&vt[mb+3]);
        #pragma unroll
        for (int r = 0; r < ROWS; r++) {
            float4 ss = *(const float4*)(scf + r * NTOK + mb);
            float w0 = (ss.x >= thrf[r]) ? __expf(ss.x - Mr[r]) : 0.f;
            float w1 = (ss.y >= thrf[r]) ? __expf(ss.y - Mr[r]) : 0.f;
            float w2 = (ss.z >= thrf[r]) ? __expf(ss.z - Mr[r]) : 0.f;
            float w3 = (ss.w >= thrf[r]) ? __expf(ss.w - Mr[r]) : 0.f;
            zz[r] += ((w0 + w1) + (w2 + w3));
            acc[r].x += w0*v0.x + w1*v1.x + w2*v2.x + w3*v3.x;
            acc[r].y += w0*v0.y + w1*v1.y + w2*v2.y + w3*v3.y;
            acc[r].z += w0*v0.z + w1*v1.z + w2*v2.z + w3*v3.z;
            acc[r].w += w0*v0.w + w1*v1.w + w2*v2.w + w3*v3.w;
        }
    }

    // block-reduce 20 accumulators
    float vals[20];
    #pragma unroll
    for (int r = 0; r < ROWS; r++) {
        vals[r*5 + 0] = zz[r];
        vals[r*5 + 1] = acc[r].x; vals[r*5 + 2] = acc[r].y;
        vals[r*5 + 3] = acc[r].z; vals[r*5 + 4] = acc[r].w;
    }
    #pragma unroll
    for (int q = 0; q < 20; q++)
        for (int off = 16; off; off >>= 1)
            vals[q] += __shfl_down_sync(0xffffffffu, vals[q], off);
    if (lane == 0) {
        #pragma unroll
        for (int q = 0; q < 20; q++) sred[q*8 + wid] = vals[q];
    }
    __syncthreads();
    if (tid < 20) {
        float s = 0.f;
        for (int w = 0; w < 8; w++) s += sred[tid*8 + w];
        sfin[tid] = s;
    }
    __syncthreads();
    if (tid < 16) {
        int r = tid >> 2, c = tid & 3;
        float val = sfin[r*5 + 1 + c] / sfin[r*5 + 0];
        int n = n0 + r;
        int tt = n & 3, pixel = n >> 2;
        int ch = tt * 32 + head * 4 + c;
        g_pre[ch * 1024 + pixel] = val;
    }
}

// ---------------- kernel 4: final 1x1 projection ----------------
__global__ void proj_kernel(const float* __restrict__ wproj, float* __restrict__ out) {
    int idx = blockIdx.x * THREADS + threadIdx.x;
    int o = idx >> 10, p = idx & 1023;
    const float* w = wproj + o * 128;
    float s = 0.f;
    #pragma unroll 8
    for (int ch = 0; ch < 128; ch++) s += w[ch] * g_pre[ch * 1024 + p];
    out[idx] = s;
}

// ---------------- launch ----------------
extern "C" void kernel_launch(void* const* d_in, const int* in_sizes, int n_in,
                              void* d_out, int out_size) {
    (void)in_sizes; (void)n_in; (void)out_size;
    const float* x           = (const float*)d_in[0];
    const float* temperature = (const float*)d_in[1];
    const float* wqkv        = (const float*)d_in[2];
    const float* wdw         = (const float*)d_in[3];
    const float* wproj       = (const float*)d_in[4];
    float* out = (float*)d_out;

    cudaFuncSetAttribute(attn_kernel, cudaFuncAttributeMaxDynamicSharedMemorySize, SMEM_BYTES);

    prep_kernel<<<dim3(12, 32), THREADS>>>(x, wqkv, wdw);
    norm_kernel<<<72, THREADS>>>();
    attn_kernel<<<HEADS * (NTOK / ROWS), THREADS, SMEM_BYTES>>>(temperature);
    proj_kernel<<<(128 * 1024) / THREADS, THREADS>>>(wproj, out);
}